// round 17
// baseline (speedup 1.0000x reference)
#include <cuda_runtime.h>

#define BB   32
#define NN   2048
#define KK   16
#define FIN  32
#define FOUT 64
#define NPTS (BB * NN)          // 65536
#define PAD  4
#define NS   (NN + 2 * PAD)     // 2056
#define QPW  8                  // queries per block (one per warp)
#define KNN_THREADS 256
#define KNN_SMEM (NS * 16 + 64 * 32)   // 34944 B: tile + 64 AABBs

// Scratch (allocation-free rule: __device__ globals)
__device__ float4 g_sorted[BB * NS];
__device__ float  g_a[NPTS * FOUT];
__device__ float  g_c[NPTS * FOUT];
__device__ float  g_s[NPTS * FOUT];
__device__ int    g_idx[NPTS * KK];

// ---------------------------------------------------------------------------
__device__ __forceinline__ unsigned spread3(unsigned x) {
    x &= 0x3FF;
    x = (x | (x << 16)) & 0x030000FF;
    x = (x | (x << 8))  & 0x0300F00F;
    x = (x | (x << 4))  & 0x030C30C3;
    x = (x | (x << 2))  & 0x09249249;
    return x;
}

// ---------------------------------------------------------------------------
// Kernel 0: per-batch Morton sort (7 bits/dim). Bitonic on packed uint32 keys.
// ---------------------------------------------------------------------------
__global__ __launch_bounds__(1024) void sort_kernel(const float* __restrict__ pos) {
    __shared__ float4   spp[NN];
    __shared__ unsigned key[NN];
    __shared__ float    s_red[6][32];
    __shared__ float    s_bounds[6];

    const int b    = blockIdx.x;
    const int tid  = threadIdx.x;
    const int lane = tid & 31;
    const int wid  = tid >> 5;

    for (int i = tid; i < NN; i += 1024) {
        const float* p = pos + (size_t)(b * NN + i) * 3;
        spp[i] = make_float4(p[0], p[1], p[2], __int_as_float(i));
    }
    __syncthreads();

    float mn[3] = { 3e38f, 3e38f, 3e38f }, mx[3] = { -3e38f, -3e38f, -3e38f };
    for (int i = tid; i < NN; i += 1024) {
        float4 q = spp[i];
        mn[0] = fminf(mn[0], q.x); mx[0] = fmaxf(mx[0], q.x);
        mn[1] = fminf(mn[1], q.y); mx[1] = fmaxf(mx[1], q.y);
        mn[2] = fminf(mn[2], q.z); mx[2] = fmaxf(mx[2], q.z);
    }
#pragma unroll
    for (int o = 16; o; o >>= 1) {
#pragma unroll
        for (int d = 0; d < 3; d++) {
            mn[d] = fminf(mn[d], __shfl_xor_sync(0xFFFFFFFFu, mn[d], o));
            mx[d] = fmaxf(mx[d], __shfl_xor_sync(0xFFFFFFFFu, mx[d], o));
        }
    }
    if (lane == 0) {
#pragma unroll
        for (int d = 0; d < 3; d++) { s_red[d][wid] = mn[d]; s_red[3 + d][wid] = mx[d]; }
    }
    __syncthreads();
    if (tid < 32) {
        float v0 = s_red[0][tid], v1 = s_red[1][tid], v2 = s_red[2][tid];
        float v3 = s_red[3][tid], v4 = s_red[4][tid], v5 = s_red[5][tid];
#pragma unroll
        for (int o = 16; o; o >>= 1) {
            v0 = fminf(v0, __shfl_xor_sync(0xFFFFFFFFu, v0, o));
            v1 = fminf(v1, __shfl_xor_sync(0xFFFFFFFFu, v1, o));
            v2 = fminf(v2, __shfl_xor_sync(0xFFFFFFFFu, v2, o));
            v3 = fmaxf(v3, __shfl_xor_sync(0xFFFFFFFFu, v3, o));
            v4 = fmaxf(v4, __shfl_xor_sync(0xFFFFFFFFu, v4, o));
            v5 = fmaxf(v5, __shfl_xor_sync(0xFFFFFFFFu, v5, o));
        }
        if (tid == 0) {
            s_bounds[0] = v0; s_bounds[1] = v1; s_bounds[2] = v2;
            s_bounds[3] = 127.0f / fmaxf(v3 - v0, 1e-12f);
            s_bounds[4] = 127.0f / fmaxf(v4 - v1, 1e-12f);
            s_bounds[5] = 127.0f / fmaxf(v5 - v2, 1e-12f);
        }
    }
    __syncthreads();

    const float mnx = s_bounds[0], mny = s_bounds[1], mnz = s_bounds[2];
    const float sx = s_bounds[3], sy = s_bounds[4], sz = s_bounds[5];
    for (int i = tid; i < NN; i += 1024) {
        float4 q = spp[i];
        unsigned ux = (unsigned)min(max((int)((q.x - mnx) * sx), 0), 127);
        unsigned uy = (unsigned)min(max((int)((q.y - mny) * sy), 0), 127);
        unsigned uz = (unsigned)min(max((int)((q.z - mnz) * sz), 0), 127);
        unsigned code = spread3(ux) | (spread3(uy) << 1) | (spread3(uz) << 2);
        key[i] = (code << 11) | (unsigned)i;
    }

    for (int k = 2; k <= NN; k <<= 1) {
        for (int j = k >> 1; j > 0; j >>= 1) {
            __syncthreads();
            int l = ((tid & ~(j - 1)) << 1) | (tid & (j - 1));
            int p = l | j;
            unsigned A = key[l], Bv = key[p];
            bool asc = (l & k) == 0;
            if ((A > Bv) == asc) { key[l] = Bv; key[p] = A; }
        }
    }
    __syncthreads();

    float4* gs = g_sorted + (size_t)b * NS;
    for (int i = tid; i < NN; i += 1024) gs[PAD + i] = spp[key[i] & 0x7FF];
    if (tid < PAD) {
        gs[tid]            = make_float4(-1.0e30f, -1.0e30f, -1.0e30f, __int_as_float(0));
        gs[PAD + NN + tid] = make_float4( 1.0e30f,  1.0e30f,  1.0e30f, __int_as_float(0));
    }
}

// ---------------------------------------------------------------------------
__device__ __forceinline__ void ins16(float dk[KK], float v) {
#pragma unroll
    for (int k = 0; k < KK; k++) {
        float lo = fminf(dk[k], v);
        v = fmaxf(dk[k], v);
        dk[k] = lo;
    }
}

// Merge my ascending dk[16] with xor-partner's: keep 16 smallest, re-sorted.
__device__ __forceinline__ void merge16(float dk[KK], int lanemask) {
    float o[KK];
#pragma unroll
    for (int i = 0; i < KK; i++)
        o[i] = __shfl_xor_sync(0xFFFFFFFFu, dk[KK - 1 - i], lanemask);
#pragma unroll
    for (int i = 0; i < KK; i++) dk[i] = fminf(dk[i], o[i]);
#pragma unroll
    for (int d = 8; d >= 1; d >>= 1) {
#pragma unroll
        for (int i = 0; i < KK; i++) {
            if ((i & d) == 0) {
                float lo = fminf(dk[i], dk[i | d]);
                float hi = fmaxf(dk[i], dk[i | d]);
                dk[i] = lo; dk[i | d] = hi;
            }
        }
    }
}

// ---------------------------------------------------------------------------
// Kernel 1: exact kNN, ONE WARP PER QUERY. All control flow warp-uniform.
//  A) +-32 Morton window (lane s=lane+1, both sides); ladder -> exact t0.
//  B) lane tests AABB of words lane and lane+32; ballots -> surviving-word
//     set sw (identical in all lanes) -> uniform word loops below.
//  C) per surviving word: lane handles candidate word*32+lane; branchless
//     ins16(valid ? d2 : inf); ladder -> exact tau.
//  E) same uniform loop; ballot + prefix-popc slot assignment (no atomics).
// ---------------------------------------------------------------------------
__global__ __launch_bounds__(KNN_THREADS) void knn_kernel() {
    extern __shared__ unsigned char dynsmem[];
    float4* sp   = reinterpret_cast<float4*>(dynsmem);
    float4* sbox = reinterpret_cast<float4*>(dynsmem + NS * 16);

    const int blk  = blockIdx.x;
    const int b    = blk >> 8;              // 256 blocks per batch
    const int part = blk & 255;
    const int t    = threadIdx.x;
    const int w    = t >> 5;                // warp 0..7 = query slot
    const int lane = t & 31;

    const float4* gs = g_sorted + (size_t)b * NS;
    for (int i = t; i < NS; i += KNN_THREADS) sp[i] = gs[i];
    __syncthreads();

    // word AABBs (threads 0..63, one word each)
    if (t < 64) {
        const int jb = PAD + (t << 5);
        float4 p0 = sp[jb];
        float mnx = p0.x, mxx = p0.x, mny = p0.y, mxy = p0.y, mnz = p0.z, mxz = p0.z;
#pragma unroll 4
        for (int i = 1; i < 32; i++) {
            float4 p = sp[jb + i];
            mnx = fminf(mnx, p.x); mxx = fmaxf(mxx, p.x);
            mny = fminf(mny, p.y); mxy = fmaxf(mxy, p.y);
            mnz = fminf(mnz, p.z); mxz = fmaxf(mxz, p.z);
        }
        sbox[(t << 1)]     = make_float4(mnx, mny, mnz, 0.f);
        sbox[(t << 1) + 1] = make_float4(mxx, mxy, mxz, 0.f);
    }
    __syncthreads();

    const int rank = (part << 3) + w;       // part*QPW + warp
    const int ic   = PAD + rank;
    const float4 me = sp[ic];

    // ---- A: exact t0 from +-32 window (2 candidates per lane) ----
    float dk[KK];
#pragma unroll
    for (int k = 0; k < KK; k++) dk[k] = 3.0e38f;
    {
        const int s = lane + 1;             // 1..32
        const int il = max(ic - s, 0);
        const int ir = min(ic + s, NS - 1);
        float4 ql = sp[il];
        float4 qr = sp[ir];
        float dxl = me.x - ql.x, dyl = me.y - ql.y, dzl = me.z - ql.z;
        float dxr = me.x - qr.x, dyr = me.y - qr.y, dzr = me.z - qr.z;
        float d2l = fmaf(dxl, dxl, fmaf(dyl, dyl, dzl * dzl));
        float d2r = fmaf(dxr, dxr, fmaf(dyr, dyr, dzr * dzr));
        ins16(dk, d2l);
        ins16(dk, d2r);
    }
    merge16(dk, 1); merge16(dk, 2); merge16(dk, 4); merge16(dk, 8); merge16(dk, 16);
    const float t0  = dk[KK - 1];
    const float t0b = t0 * 1.0001f;         // box-test slack absorbs fp rounding

    // ---- B: lane-distributed box tests -> warp-shared surviving-word set ----
    unsigned sw_lo, sw_hi;
    {
        float4 bmn = sbox[(lane << 1)];
        float4 bmx = sbox[(lane << 1) + 1];
        float ex = fmaxf(fmaxf(bmn.x - me.x, me.x - bmx.x), 0.f);
        float ey = fmaxf(fmaxf(bmn.y - me.y, me.y - bmx.y), 0.f);
        float ez = fmaxf(fmaxf(bmn.z - me.z, me.z - bmx.z), 0.f);
        float lb0 = fmaf(ex, ex, fmaf(ey, ey, ez * ez));
        float4 cmn = sbox[((lane + 32) << 1)];
        float4 cmx = sbox[((lane + 32) << 1) + 1];
        float fx = fmaxf(fmaxf(cmn.x - me.x, me.x - cmx.x), 0.f);
        float fy = fmaxf(fmaxf(cmn.y - me.y, me.y - cmx.y), 0.f);
        float fz = fmaxf(fmaxf(cmn.z - me.z, me.z - cmx.z), 0.f);
        float lb1 = fmaf(fx, fx, fmaf(fy, fy, fz * fz));
        sw_lo = __ballot_sync(0xFFFFFFFFu, lb0 <= t0b);
        sw_hi = __ballot_sync(0xFFFFFFFFu, lb1 <= t0b);
    }

    // ---- C: exact tau over candidates in surviving words ----
#pragma unroll
    for (int k = 0; k < KK; k++) dk[k] = 3.0e38f;
    {
        unsigned m0 = sw_lo;
        while (m0) {                        // warp-uniform loop
            int wd = __ffs(m0) - 1; m0 &= m0 - 1;
            int cand = (wd << 5) + lane;
            float4 p = sp[PAD + cand];
            float dx = me.x - p.x, dy = me.y - p.y, dz = me.z - p.z;
            float d2 = fmaf(dx, dx, fmaf(dy, dy, dz * dz));
            bool valid = (d2 <= t0) && (cand != rank);
            ins16(dk, valid ? d2 : 3.0e38f);
        }
        unsigned m1 = sw_hi;
        while (m1) {
            int wd = (__ffs(m1) - 1) + 32; m1 &= m1 - 1;
            int cand = (wd << 5) + lane;
            float4 p = sp[PAD + cand];
            float dx = me.x - p.x, dy = me.y - p.y, dz = me.z - p.z;
            float d2 = fmaf(dx, dx, fmaf(dy, dy, dz * dz));
            bool valid = (d2 <= t0) && (cand != rank);
            ins16(dk, valid ? d2 : 3.0e38f);
        }
    }
    merge16(dk, 1); merge16(dk, 2); merge16(dk, 4); merge16(dk, 8); merge16(dk, 16);
    const float tau = dk[KK - 1];

    // ---- E: emit via ballot + prefix popc (no atomics, order-deterministic) ----
    const int gbase = b * NN;
    int* orow = g_idx + (size_t)(gbase + __float_as_int(me.w)) * KK;
    int cnt = 0;
    const unsigned lanelt = (1u << lane) - 1u;
    {
        unsigned m0 = sw_lo;
        while (m0) {
            int wd = __ffs(m0) - 1; m0 &= m0 - 1;
            int cand = (wd << 5) + lane;
            float4 p = sp[PAD + cand];
            float dx = me.x - p.x, dy = me.y - p.y, dz = me.z - p.z;
            float d2 = fmaf(dx, dx, fmaf(dy, dy, dz * dz));
            bool acc = (d2 <= tau) && (cand != rank);
            unsigned mk = __ballot_sync(0xFFFFFFFFu, acc);
            int pos = cnt + __popc(mk & lanelt);
            if (acc && pos < KK) orow[pos] = gbase + __float_as_int(p.w);
            cnt += __popc(mk);
        }
        unsigned m1 = sw_hi;
        while (m1) {
            int wd = (__ffs(m1) - 1) + 32; m1 &= m1 - 1;
            int cand = (wd << 5) + lane;
            float4 p = sp[PAD + cand];
            float dx = me.x - p.x, dy = me.y - p.y, dz = me.z - p.z;
            float d2 = fmaf(dx, dx, fmaf(dy, dy, dz * dz));
            bool acc = (d2 <= tau) && (cand != rank);
            unsigned mk = __ballot_sync(0xFFFFFFFFu, acc);
            int pos = cnt + __popc(mk & lanelt);
            if (acc && pos < KK) orow[pos] = gbase + __float_as_int(p.w);
            cnt += __popc(mk);
        }
    }
    // safety fill (ties/degenerate; normally cnt >= 16)
    if (lane == 0 && cnt < KK) {
        int f = (cnt > 0) ? orow[0] : gbase;
        for (int k = cnt; k < KK; k++) orow[k] = f;
    }
}

// ---------------------------------------------------------------------------
// Kernel 2: per-node transforms. a = x@(W1-W2)+b_e, c = x@W2, s = relu(x@Wn+bn)
// ---------------------------------------------------------------------------
__global__ __launch_bounds__(128) void transform_kernel(
    const float* __restrict__ x,
    const float* __restrict__ We,
    const float* __restrict__ be,
    const float* __restrict__ Wn,
    const float* __restrict__ bn)
{
    __shared__ float s_wd[FIN * FOUT];
    __shared__ float s_w2[FIN * FOUT];
    __shared__ float s_wn[FIN * FOUT];
    __shared__ float s_be[FOUT];
    __shared__ float s_bn[FOUT];

    const int tid = threadIdx.x;
    for (int t = tid; t < FIN * FOUT; t += 128) {
        float w2 = We[FIN * FOUT + t];
        s_w2[t] = w2;
        s_wd[t] = We[t] - w2;
        s_wn[t] = Wn[t];
    }
    if (tid < FOUT) { s_be[tid] = be[tid]; s_bn[tid] = bn[tid]; }
    __syncthreads();

    const int node = blockIdx.x * 128 + tid;

    float xr[FIN];
#pragma unroll
    for (int r = 0; r < FIN; r += 4) {
        float4 v = *reinterpret_cast<const float4*>(x + (size_t)node * FIN + r);
        xr[r] = v.x; xr[r + 1] = v.y; xr[r + 2] = v.z; xr[r + 3] = v.w;
    }

    for (int f0 = 0; f0 < FOUT; f0 += 4) {
        float a0 = s_be[f0], a1 = s_be[f0 + 1], a2 = s_be[f0 + 2], a3 = s_be[f0 + 3];
        float c0 = 0.f, c1 = 0.f, c2 = 0.f, c3 = 0.f;
        float k0 = s_bn[f0], k1 = s_bn[f0 + 1], k2 = s_bn[f0 + 2], k3 = s_bn[f0 + 3];
#pragma unroll
        for (int r = 0; r < FIN; r++) {
            float xv = xr[r];
            float4 wd = *reinterpret_cast<const float4*>(&s_wd[r * FOUT + f0]);
            float4 w2 = *reinterpret_cast<const float4*>(&s_w2[r * FOUT + f0]);
            float4 wn = *reinterpret_cast<const float4*>(&s_wn[r * FOUT + f0]);
            a0 = fmaf(xv, wd.x, a0); a1 = fmaf(xv, wd.y, a1);
            a2 = fmaf(xv, wd.z, a2); a3 = fmaf(xv, wd.w, a3);
            c0 = fmaf(xv, w2.x, c0); c1 = fmaf(xv, w2.y, c1);
            c2 = fmaf(xv, w2.z, c2); c3 = fmaf(xv, w2.w, c3);
            k0 = fmaf(xv, wn.x, k0); k1 = fmaf(xv, wn.y, k1);
            k2 = fmaf(xv, wn.z, k2); k3 = fmaf(xv, wn.w, k3);
        }
        size_t o = (size_t)node * FOUT + f0;
        *reinterpret_cast<float4*>(&g_a[o]) = make_float4(a0, a1, a2, a3);
        *reinterpret_cast<float4*>(&g_c[o]) = make_float4(c0, c1, c2, c3);
        *reinterpret_cast<float4*>(&g_s[o]) = make_float4(fmaxf(k0, 0.f), fmaxf(k1, 0.f),
                                                          fmaxf(k2, 0.f), fmaxf(k3, 0.f));
    }
}

// ---------------------------------------------------------------------------
// Kernel 3: aggregation, float4 per thread (4 features).
// ---------------------------------------------------------------------------
__global__ __launch_bounds__(256) void aggregate_kernel(float* __restrict__ out) {
    const int gid = blockIdx.x * 256 + threadIdx.x;
    const int i  = gid >> 4;
    const int f4 = (gid & 15) << 2;

    const int4* r4 = reinterpret_cast<const int4*>(g_idx + (size_t)i * KK);
    int4 j0 = r4[0], j1 = r4[1], j2 = r4[2], j3 = r4[3];
    int jj[KK] = { j0.x, j0.y, j0.z, j0.w, j1.x, j1.y, j1.z, j1.w,
                   j2.x, j2.y, j2.z, j2.w, j3.x, j3.y, j3.z, j3.w };

    float4 m = make_float4(-3.0e38f, -3.0e38f, -3.0e38f, -3.0e38f);
#pragma unroll
    for (int k = 0; k < KK; k++) {
        float4 v = *reinterpret_cast<const float4*>(&g_c[(size_t)jj[k] * FOUT + f4]);
        m.x = fmaxf(m.x, v.x); m.y = fmaxf(m.y, v.y);
        m.z = fmaxf(m.z, v.z); m.w = fmaxf(m.w, v.w);
    }

    const size_t o = (size_t)i * FOUT + f4;
    float4 a = *reinterpret_cast<const float4*>(&g_a[o]);
    float4 s = *reinterpret_cast<const float4*>(&g_s[o]);
    float4 r;
    r.x = fmaxf(m.x + a.x, 0.f) + s.x;
    r.y = fmaxf(m.y + a.y, 0.f) + s.y;
    r.z = fmaxf(m.z + a.z, 0.f) + s.z;
    r.w = fmaxf(m.w + a.w, 0.f) + s.w;
    *reinterpret_cast<float4*>(&out[o]) = r;
}

// ---------------------------------------------------------------------------
extern "C" void kernel_launch(void* const* d_in, const int* in_sizes, int n_in,
                              void* d_out, int out_size) {
    const float* x   = (const float*)d_in[0];
    const float* pos = (const float*)d_in[1];
    const float* We  = (const float*)d_in[2];
    const float* be  = (const float*)d_in[3];
    const float* Wn  = (const float*)d_in[4];
    const float* bn  = (const float*)d_in[5];
    float* out = (float*)d_out;

    cudaFuncSetAttribute(knn_kernel, cudaFuncAttributeMaxDynamicSharedMemorySize, KNN_SMEM);

    sort_kernel<<<BB, 1024>>>(pos);
    knn_kernel<<<BB * (NN / QPW), KNN_THREADS, KNN_SMEM>>>();
    transform_kernel<<<NPTS / 128, 128>>>(x, We, be, Wn, bn);
    aggregate_kernel<<<(NPTS * FOUT / 4) / 256, 256>>>(out);
}